// round 5
// baseline (speedup 1.0000x reference)
#include <cuda_runtime.h>
#include <cstdint>

// CrossModalCenterLoss:
//   loss = (sum_b clip(||x_b - centers[labels_b]||^2, 1e-12, 1e12)) / B
//        + (C-1) * 1e-12
//
// Inputs: x [4096,256] f32, labels [4096] int32, centers [10000,256] f32.
// Output: scalar f32.
//
// Shape: 512 blocks x 256 threads, one row per warp (empirically fastest
// data phase). Cross-block reduction via per-block slots + ticket counter:
// no same-address atomic serialization; last block gathers 512 slots.

#define BATCH_N   4096
#define NUM_CLS   10000
#define FEAT_D    256
#define CLAMP_LO  1e-12f
#define CLAMP_HI  1e12f
#define WARPS_PER_BLK 8
#define GRID_BLKS (BATCH_N / WARPS_PER_BLK)   // 512

__device__ float    g_part[GRID_BLKS];
__device__ unsigned g_count = 0u;

__global__ __launch_bounds__(256) void cmcl_main(
    const float* __restrict__ x,
    const int* __restrict__ labels,
    const float* __restrict__ centers,
    float* __restrict__ out)
{
    const int warp = threadIdx.x >> 5;
    const int lane = threadIdx.x & 31;
    const int row  = blockIdx.x * WARPS_PER_BLK + warp;

    // Label broadcast load first (center gather depends on it), x loads
    // issued independently to overlap the label fetch.
    int lbl = labels[row];
    const float4* xr = reinterpret_cast<const float4*>(x + (size_t)row * FEAT_D);
    float4 a0 = xr[lane];
    float4 a1 = xr[lane + 32];

    lbl = max(0, min(NUM_CLS - 1, lbl));     // never fault on a bad label
    const float4* cr = reinterpret_cast<const float4*>(centers + (size_t)lbl * FEAT_D);
    float4 b0 = cr[lane];
    float4 b1 = cr[lane + 32];

    float d;
    float acc;
    d = a0.x - b0.x; acc = d * d;
    d = a0.y - b0.y; acc = fmaf(d, d, acc);
    d = a0.z - b0.z; acc = fmaf(d, d, acc);
    d = a0.w - b0.w; acc = fmaf(d, d, acc);
    d = a1.x - b1.x; acc = fmaf(d, d, acc);
    d = a1.y - b1.y; acc = fmaf(d, d, acc);
    d = a1.z - b1.z; acc = fmaf(d, d, acc);
    d = a1.w - b1.w; acc = fmaf(d, d, acc);

    // Warp reduction -> per-row squared distance.
    #pragma unroll
    for (int o = 16; o > 0; o >>= 1)
        acc += __shfl_xor_sync(0xffffffffu, acc, o);

    __shared__ float warp_sums[WARPS_PER_BLK];
    if (lane == 0)
        warp_sums[warp] = fminf(fmaxf(acc, CLAMP_LO), CLAMP_HI);
    __syncthreads();

    if (warp == 0) {
        float v = (lane < WARPS_PER_BLK) ? warp_sums[lane] : 0.0f;
        #pragma unroll
        for (int o = 4; o > 0; o >>= 1)
            v += __shfl_xor_sync(0xffffffffu, v, o);

        unsigned ticket = 0u;
        if (lane == 0) {
            g_part[blockIdx.x] = v;         // private slot: no serialization
            __threadfence();                // slot visible before ticket
            ticket = atomicAdd(&g_count, 1u);
        }
        ticket = __shfl_sync(0xffffffffu, ticket, 0);

        if (ticket == (unsigned)(GRID_BLKS - 1)) {
            // Last block: all 511 other slots are visible (fence+ticket).
            float s = 0.0f;
            #pragma unroll
            for (int i = 0; i < GRID_BLKS / 32; i++)     // 16 coalesced loads
                s += __ldcg(&g_part[i * 32 + lane]);
            #pragma unroll
            for (int o = 16; o > 0; o >>= 1)
                s += __shfl_xor_sync(0xffffffffu, s, o);
            if (lane == 0) {
                out[0] = s * (1.0f / (float)BATCH_N)
                       + (float)(NUM_CLS - 1) * CLAMP_LO;
                g_count = 0u;               // reset for next graph replay
            }
        }
    }
}

extern "C" void kernel_launch(void* const* d_in, const int* in_sizes, int n_in,
                              void* d_out, int out_size) {
    const float* x       = (const float*)d_in[0];
    const int*   labels  = (const int*)d_in[1];
    const float* centers = (const float*)d_in[2];
    float*       out     = (float*)d_out;
    (void)in_sizes; (void)n_in; (void)out_size;

    cmcl_main<<<GRID_BLKS, 256>>>(x, labels, centers, out);
}